// round 2
// baseline (speedup 1.0000x reference)
#include <cuda_runtime.h>
#include <cstdint>

// Problem constants
#define B_  16
#define T_  256
#define E_  512
#define H_  1024
#define V_  32000
#define H3  3072          // 3*H
#define KS_ 8             // K-splits for the recurrent gh GEMM

// ---------------------------------------------------------------------------
// Static device scratch (allocation-free contract: __device__ globals)
// ---------------------------------------------------------------------------
__device__ float g_GX0[(size_t)4096 * 3072];   // gx for layer0, rows m = t*B+b (bias included)
__device__ float g_Gpart[KS_ * 16 * 3072];     // K-split partials of h0 @ Wh0 for one step
__device__ float g_H0[(size_t)4096 * 1024];    // h0 sequence, rows m = t*B+b
__device__ float g_G1x[(size_t)4096 * 3072];   // h0seq @ Wx1 + bx1
__device__ float g_G1h[(size_t)4096 * 3072];   // h0seq @ Wh1 + bh1
__device__ float g_H1[(size_t)4096 * 1024];    // h1 sequence, rows m = t*B+b

// Compile-time selectors for device-global scratch (avoids cudaGetSymbolAddress
// in the capture path: kernel_launch is then launches ONLY).
#define BUF_EXT  0   // use pointer argument
#define BUF_GX0  1
#define BUF_H0   2
#define BUF_G1X  3
#define BUF_G1H  4
#define BUF_H1   5

template<int SEL>
__device__ __forceinline__ float* buf_ptr(float* ext) {
    if (SEL == BUF_GX0) return g_GX0;
    if (SEL == BUF_H0)  return g_H0;
    if (SEL == BUF_G1X) return g_G1x;
    if (SEL == BUF_G1H) return g_G1h;
    if (SEL == BUF_H1)  return g_H1;
    return ext;
}

__device__ __forceinline__ float sigmoidf_(float x) { return 1.0f / (1.0f + __expf(-x)); }

// ---------------------------------------------------------------------------
// Generic 128x128x8 register-tiled SGEMM: C = A @ B + bias
//  - GATHER:  A row m is emb[x[(m%16)*256 + m/16]]  (embedding fused into GEMM)
//  - PERMUTE: output row for m = t*16+b is written at b*256+t (logits [B,T,V] layout)
// A source and C destination are selected at compile time (device globals or
// external pointers). Requires M%128==0, N%128==0, K%8==0 (true for all calls).
// ---------------------------------------------------------------------------
template<int ASEL, int CSEL, bool GATHER, bool PERMUTE>
__global__ __launch_bounds__(256) void gemm_k(
    const float* __restrict__ Aext, const float* __restrict__ Bm,
    const float* __restrict__ bias, float* __restrict__ Cext,
    const int* __restrict__ xidx, int M, int N, int K)
{
    __shared__ float As[8][132];   // padded: store stride 132 avoids bank conflicts
    __shared__ float Bs[8][128];

    const float* A = buf_ptr<ASEL>(const_cast<float*>(Aext));
    float*       C = buf_ptr<CSEL>(Cext);

    const int tid = threadIdx.x;
    const int tx  = tid & 15;        // 0..15 -> 8 output cols each
    const int ty  = tid >> 4;        // 0..15 -> 8 output rows each
    const int m0  = blockIdx.y * 128;
    const int n0  = blockIdx.x * 128;

    // A-tile load mapping: 128 rows x 8 k, one float4 per thread
    const int lm = tid >> 1;         // 0..127 local row
    const int lk = (tid & 1) * 4;    // 0 or 4
    // B-tile load mapping: 8 k-rows x 128 n, one float4 per thread
    const int bk = tid >> 5;         // 0..7
    const int bn = (tid & 31) * 4;   // 0..124

    const float* arow;
    {
        int m = m0 + lm;
        if (GATHER) {
            int xi = xidx[(m & (B_ - 1)) * T_ + (m >> 4)];
            arow = A + (size_t)xi * K;
        } else {
            arow = A + (size_t)m * K;
        }
    }

    float acc[8][8];
#pragma unroll
    for (int i = 0; i < 8; i++)
#pragma unroll
        for (int j = 0; j < 8; j++) acc[i][j] = 0.0f;

    for (int k0 = 0; k0 < K; k0 += 8) {
        float4 av = *reinterpret_cast<const float4*>(arow + k0 + lk);
        float4 bv = *reinterpret_cast<const float4*>(Bm + (size_t)(k0 + bk) * N + n0 + bn);
        As[lk + 0][lm] = av.x;
        As[lk + 1][lm] = av.y;
        As[lk + 2][lm] = av.z;
        As[lk + 3][lm] = av.w;
        *reinterpret_cast<float4*>(&Bs[bk][bn]) = bv;
        __syncthreads();

#pragma unroll
        for (int kk = 0; kk < 8; kk++) {
            float4 a0 = *reinterpret_cast<const float4*>(&As[kk][ty * 8]);
            float4 a1 = *reinterpret_cast<const float4*>(&As[kk][ty * 8 + 4]);
            float4 b0 = *reinterpret_cast<const float4*>(&Bs[kk][tx * 8]);
            float4 b1 = *reinterpret_cast<const float4*>(&Bs[kk][tx * 8 + 4]);
            float a_[8] = {a0.x, a0.y, a0.z, a0.w, a1.x, a1.y, a1.z, a1.w};
            float b_[8] = {b0.x, b0.y, b0.z, b0.w, b1.x, b1.y, b1.z, b1.w};
#pragma unroll
            for (int i = 0; i < 8; i++)
#pragma unroll
                for (int j = 0; j < 8; j++)
                    acc[i][j] += a_[i] * b_[j];
        }
        __syncthreads();
    }

    // epilogue: bias + store (optionally row-permuted)
#pragma unroll
    for (int i = 0; i < 8; i++) {
        int m = m0 + ty * 8 + i;
        int orow = PERMUTE ? ((m & (B_ - 1)) * T_ + (m >> 4)) : m;
        float* crow = C + (size_t)orow * N + n0 + tx * 8;
#pragma unroll
        for (int j = 0; j < 8; j++)
            crow[j] = acc[i][j] + bias[n0 + tx * 8 + j];
    }
}

// ---------------------------------------------------------------------------
// Recurrent step, stage 1: partial gh = h_prev[16,1024] @ Wh0[1024,3072]
// grid (24 n-tiles of 128, 8 k-splits of 128), block 256.
// Each thread: 1 row x 8 cols -> per kk: 1 LDS.32 + 2 LDS.128 + 8 FMA (FMA-bound).
// ---------------------------------------------------------------------------
__global__ __launch_bounds__(256) void gru0_gh_partial(
    const float* __restrict__ Wh, int t)
{
    __shared__ float Hs[16][17];     // Hs[kk][row], padded
    __shared__ float Ws[16][128];

    const float* hprev = g_H0 + (size_t)(t - 1) * B_ * H_;

    const int tid = threadIdx.x;
    const int n0   = blockIdx.x * 128;
    const int kbeg = blockIdx.y * 128;
    const int r  = tid >> 4;          // 0..15 output row
    const int c0 = (tid & 15) * 8;    // 8 output cols

    float acc[8];
#pragma unroll
    for (int j = 0; j < 8; j++) acc[j] = 0.0f;

    for (int k0 = kbeg; k0 < kbeg + 128; k0 += 16) {
        // h_prev tile [16 rows][16 k], transposed into Hs[kk][row]
        Hs[tid & 15][tid >> 4] = hprev[(size_t)(tid >> 4) * H_ + k0 + (tid & 15)];
        // W tile [16 k][128 n], 2 float4 per thread
#pragma unroll
        for (int i = 0; i < 2; i++) {
            int kk = (tid >> 5) + i * 8;
            int cc = (tid & 31) * 4;
            *reinterpret_cast<float4*>(&Ws[kk][cc]) =
                *reinterpret_cast<const float4*>(&Wh[(size_t)(k0 + kk) * H3 + n0 + cc]);
        }
        __syncthreads();
#pragma unroll
        for (int kk = 0; kk < 16; kk++) {
            float h = Hs[kk][r];
            float4 w0 = *reinterpret_cast<const float4*>(&Ws[kk][c0]);
            float4 w1 = *reinterpret_cast<const float4*>(&Ws[kk][c0 + 4]);
            acc[0] += h * w0.x; acc[1] += h * w0.y;
            acc[2] += h * w0.z; acc[3] += h * w0.w;
            acc[4] += h * w1.x; acc[5] += h * w1.y;
            acc[6] += h * w1.z; acc[7] += h * w1.w;
        }
        __syncthreads();
    }

    float* out = g_Gpart + (size_t)blockIdx.y * (16 * H3) + (size_t)r * H3 + n0 + c0;
#pragma unroll
    for (int j = 0; j < 8; j++) out[j] = acc[j];
}

// ---------------------------------------------------------------------------
// Recurrent step, stage 2: reduce K-split partials + GRU cell -> H0[t]
// 16384 threads (one per (b, j)).
// ---------------------------------------------------------------------------
__global__ void gru0_combine(const float* __restrict__ bh0, int t)
{
    int i = blockIdx.x * blockDim.x + threadIdx.x;   // 0..B*H-1
    int b = i >> 10;
    int j = i & (H_ - 1);

    float ghr = bh0[j], ghz = bh0[H_ + j], ghn = bh0[2 * H_ + j];
    if (t > 0) {
#pragma unroll
        for (int ks = 0; ks < KS_; ks++) {
            const float* gp = g_Gpart + (size_t)ks * (16 * H3) + (size_t)b * H3 + j;
            ghr += gp[0];
            ghz += gp[H_];
            ghn += gp[2 * H_];
        }
    }
    const float* gx = g_GX0 + (size_t)(t * B_ + b) * H3 + j;
    float r = sigmoidf_(gx[0]      + ghr);
    float z = sigmoidf_(gx[H_]     + ghz);
    float n = tanhf   (gx[2 * H_] + r * ghn);
    float hp = (t > 0) ? g_H0[(size_t)((t - 1) * B_ + b) * H_ + j] : 0.0f;
    g_H0[(size_t)(t * B_ + b) * H_ + j] = (1.0f - z) * n + z * hp;
}

// ---------------------------------------------------------------------------
// Layer-1 GRU elementwise (input == hidden == h0seq, reproducing reference bug)
// ---------------------------------------------------------------------------
__global__ void gru1_elem()
{
    size_t i = (size_t)blockIdx.x * blockDim.x + threadIdx.x;  // < 4096*1024
    size_t m = i >> 10;
    int    j = (int)(i & (H_ - 1));
    const float* gx = g_G1x + m * H3 + j;
    const float* gh = g_G1h + m * H3 + j;
    float r = sigmoidf_(gx[0]      + gh[0]);
    float z = sigmoidf_(gx[H_]     + gh[H_]);
    float n = tanhf   (gx[2 * H_] + r * gh[2 * H_]);
    float h = g_H0[i];
    g_H1[i] = (1.0f - z) * n + z * h;
}

// ---------------------------------------------------------------------------
// Final hidden states: d_out[B*T*V ..] = stack(h0_final, h1_final)
// ---------------------------------------------------------------------------
__global__ void write_hidden(float* __restrict__ out)
{
    int i = blockIdx.x * blockDim.x + threadIdx.x;   // < 2*B*H = 32768
    size_t base = (size_t)(T_ - 1) * B_ * H_;
    float v = (i < B_ * H_) ? g_H0[base + i] : g_H1[base + (i - B_ * H_)];
    out[(size_t)B_ * T_ * V_ + i] = v;
}

// ---------------------------------------------------------------------------
// kernel_launch: graph-capturable — kernel launches ONLY
// ---------------------------------------------------------------------------
extern "C" void kernel_launch(void* const* d_in, const int* in_sizes, int n_in,
                              void* d_out, int out_size)
{
    const int*   x   = (const int*)  d_in[0];
    const float* emb = (const float*)d_in[1];
    const float* Wx0 = (const float*)d_in[2];
    const float* Wh0 = (const float*)d_in[3];
    const float* bx0 = (const float*)d_in[4];
    const float* bh0 = (const float*)d_in[5];
    const float* Wx1 = (const float*)d_in[6];
    const float* Wh1 = (const float*)d_in[7];
    const float* bx1 = (const float*)d_in[8];
    const float* bh1 = (const float*)d_in[9];
    const float* fcW = (const float*)d_in[10];
    const float* fcb = (const float*)d_in[11];
    float* out = (float*)d_out;

    // 1) gx0 for all timesteps: gather(emb, x) @ Wx0 + bx0   [4096 x 3072]
    gemm_k<BUF_EXT, BUF_GX0, true, false><<<dim3(H3 / 128, 4096 / 128), 256>>>(
        emb, Wx0, bx0, nullptr, x, 4096, H3, E_);

    // 2) sequential layer-0 scan: 256 steps of (h0 @ Wh0) + GRU cell
    for (int t = 0; t < T_; t++) {
        if (t > 0)
            gru0_gh_partial<<<dim3(H3 / 128, KS_), 256>>>(Wh0, t);
        gru0_combine<<<(B_ * H_) / 256, 256>>>(bh0, t);
    }

    // 3) layer 1 (time-parallel): two GEMMs + elementwise GRU
    gemm_k<BUF_H0, BUF_G1X, false, false><<<dim3(H3 / 128, 4096 / 128), 256>>>(
        nullptr, Wx1, bx1, nullptr, nullptr, 4096, H3, H_);
    gemm_k<BUF_H0, BUF_G1H, false, false><<<dim3(H3 / 128, 4096 / 128), 256>>>(
        nullptr, Wh1, bh1, nullptr, nullptr, 4096, H3, H_);
    gru1_elem<<<(4096 * 1024) / 256, 256>>>();

    // 4) logits: h1seq @ fcW + fcb, rows permuted (t*B+b) -> (b*T+t)
    gemm_k<BUF_H1, BUF_EXT, false, true><<<dim3(V_ / 128, 4096 / 128), 256>>>(
        nullptr, fcW, fcb, out, nullptr, 4096, V_, H_);

    // 5) final hidden states
    write_hidden<<<(2 * B_ * H_) / 256, 256>>>(out);
}

// round 6
// speedup vs baseline: 1.4742x; 1.4742x over previous
#include <cuda_runtime.h>
#include <cuda_bf16.h>
#include <cstdint>

// Problem constants
#define B_  16
#define T_  256
#define E_  512
#define H_  1024
#define V_  32000
#define H3  3072          // 3*H
#define KS_ 8             // K-splits for the recurrent gh GEMM
#define SCAN_BLOCKS 192   // 24 n-tiles x 8 k-tiles (co-resident: 2/SM * 148 = 296)

// ---------------------------------------------------------------------------
// Static device scratch (allocation-free contract: __device__ globals)
// ---------------------------------------------------------------------------
__device__ float g_GX0[(size_t)4096 * 3072];   // gx for layer0 (bias included)
__device__ float g_Gpart[KS_ * 16 * 3072];     // K-split partials of h0 @ Wh0
__device__ float g_H0[(size_t)4096 * 1024];    // h0 sequence, rows m = t*B+b
__device__ float g_G1x[(size_t)4096 * 3072];
__device__ float g_G1h[(size_t)4096 * 3072];
__device__ float g_H1[(size_t)4096 * 1024];

// bf16 hi/lo expanded operands (extended-K trick: [hi | lo | hi] x [hi | hi | lo])
__device__ __nv_bfloat16 g_A3[(size_t)4096 * 3072];          // activations [M][3K]
__device__ __nv_bfloat16 g_B3_Wx0[(size_t)3072 * 1536];      // [N][3K], K=512
__device__ __nv_bfloat16 g_B3_Wx1[(size_t)3072 * 3072];      // K=1024
__device__ __nv_bfloat16 g_B3_Wh1[(size_t)3072 * 3072];
__device__ __nv_bfloat16 g_B3_fcW[(size_t)32000 * 3072];

// grid-barrier state for the persistent scan kernel
__device__ unsigned g_cnt;     // zero-initialized; always returns to 0
__device__ unsigned g_gen;     // monotonically increasing generation

#define BUF_EXT  0
#define BUF_GX0  1
#define BUF_H0   2
#define BUF_G1X  3
#define BUF_G1H  4
#define BUF_H1   5

template<int SEL>
__device__ __forceinline__ float* buf_ptr(float* ext) {
    if (SEL == BUF_GX0) return g_GX0;
    if (SEL == BUF_H0)  return g_H0;
    if (SEL == BUF_G1X) return g_G1x;
    if (SEL == BUF_G1H) return g_G1h;
    if (SEL == BUF_H1)  return g_H1;
    return ext;
}

__device__ __forceinline__ float sigmoidf_(float x) { return 1.0f / (1.0f + __expf(-x)); }

__device__ __forceinline__ uint32_t smem_u32(const void* p) {
    uint32_t a;
    asm("{ .reg .u64 t; cvta.to.shared.u64 t, %1; cvt.u32.u64 %0, t; }" : "=r"(a) : "l"(p));
    return a;
}

// ---------------------------------------------------------------------------
// mma.sync / ldmatrix / cp.async helpers (all sm_80+ PTX, valid on sm_100)
// ---------------------------------------------------------------------------
__device__ __forceinline__ void ldsm_x4(uint32_t* r, uint32_t addr) {
    asm volatile("ldmatrix.sync.aligned.m8n8.x4.shared.b16 {%0,%1,%2,%3}, [%4];"
                 : "=r"(r[0]), "=r"(r[1]), "=r"(r[2]), "=r"(r[3]) : "r"(addr));
}
__device__ __forceinline__ void ldsm_x2(uint32_t* r, uint32_t addr) {
    asm volatile("ldmatrix.sync.aligned.m8n8.x2.shared.b16 {%0,%1}, [%2];"
                 : "=r"(r[0]), "=r"(r[1]) : "r"(addr));
}
__device__ __forceinline__ void mma16816(float* c, const uint32_t* a, const uint32_t* b) {
    asm volatile(
        "mma.sync.aligned.m16n8k16.row.col.f32.bf16.bf16.f32 "
        "{%0,%1,%2,%3}, {%4,%5,%6,%7}, {%8,%9}, {%0,%1,%2,%3};"
        : "+f"(c[0]), "+f"(c[1]), "+f"(c[2]), "+f"(c[3])
        : "r"(a[0]), "r"(a[1]), "r"(a[2]), "r"(a[3]), "r"(b[0]), "r"(b[1]));
}
__device__ __forceinline__ void cpa16(uint32_t saddr, const void* g) {
    asm volatile("cp.async.cg.shared.global [%0], [%1], 16;" :: "r"(saddr), "l"(g) : "memory");
}
__device__ __forceinline__ void cp_commit() {
    asm volatile("cp.async.commit_group;" ::: "memory");
}
template<int N_>
__device__ __forceinline__ void cp_wait() {
    asm volatile("cp.async.wait_group %0;" :: "n"(N_) : "memory");
}

// ---------------------------------------------------------------------------
// Conversion kernels: fp32 -> bf16 hi/lo extended-K layout
// ---------------------------------------------------------------------------
template<int ASEL, bool GATHER, int LOGK>
__global__ void conv_A3(const float* __restrict__ ext, const int* __restrict__ xidx)
{
    const int K = 1 << LOGK;
    size_t i = (size_t)blockIdx.x * blockDim.x + threadIdx.x;   // < 4096*K
    int m = (int)(i >> LOGK);
    int k = (int)(i & (K - 1));
    float v;
    if (GATHER) {
        int xi = xidx[(m & (B_ - 1)) * T_ + (m >> 4)];
        v = ext[(size_t)xi * K + k];
    } else {
        const float* src = buf_ptr<ASEL>(const_cast<float*>(ext));
        v = src[((size_t)m << LOGK) + k];
    }
    __nv_bfloat16 hi = __float2bfloat16(v);
    __nv_bfloat16 lo = __float2bfloat16(v - __bfloat162float(hi));
    size_t base = (size_t)m * (3 << LOGK) + k;
    g_A3[base]         = hi;
    g_A3[base + K]     = lo;
    g_A3[base + 2 * K] = hi;
}

// Weights: W[K][N] (row-major) -> B3[n][3K] = [hi | hi | lo] (transposed)
__global__ void conv_B3(const float* __restrict__ W, __nv_bfloat16* __restrict__ B3,
                        int K, int N)
{
    __shared__ float s[32][33];
    const int k0 = blockIdx.x * 32;
    const int n0 = blockIdx.y * 32;
    const int tx = threadIdx.x;          // 0..31
    const int ty = threadIdx.y;          // 0..7
#pragma unroll
    for (int i = 0; i < 4; i++) {
        int r = ty + i * 8;
        s[tx][r] = W[(size_t)(k0 + r) * N + n0 + tx];
    }
    __syncthreads();
    const int K3 = 3 * K;
#pragma unroll
    for (int i = 0; i < 4; i++) {
        int r = ty + i * 8;
        float v = s[r][tx];
        __nv_bfloat16 hi = __float2bfloat16(v);
        __nv_bfloat16 lo = __float2bfloat16(v - __bfloat162float(hi));
        size_t base = (size_t)(n0 + r) * K3 + k0 + tx;
        B3[base]         = hi;
        B3[base + K]     = hi;
        B3[base + 2 * K] = lo;
    }
}

// ---------------------------------------------------------------------------
// mma.sync bf16 GEMM: C[M][N] = A3[M][K3] . B3[N][K3]^T + bias
// Block 128x128, 8 warps (2x4 -> warp tile 64x32), K-chunk 32, cp.async
// double-buffered SMEM with 80B-padded rows (conflict-free ldmatrix).
// ---------------------------------------------------------------------------
#define GM_ROWB   80          // bytes per padded 32-elem bf16 row
#define GM_MATB   (128 * GM_ROWB)    // 10240 B per matrix per buffer
#define GM_BUFB   (2 * GM_MATB)      // A+B per buffer

template<int CSEL, bool PERMUTE>
__global__ __launch_bounds__(256, 2) void gemm_mma(
    const __nv_bfloat16* __restrict__ A3, const __nv_bfloat16* __restrict__ B3,
    const float* __restrict__ bias, float* __restrict__ Cext, int N, int K3)
{
    __shared__ __align__(16) char sAB[2 * GM_BUFB];   // 40960 B
    const uint32_t sb = smem_u32(sAB);

    const int tid  = threadIdx.x;
    const int wid  = tid >> 5;
    const int lane = tid & 31;
    const int wm   = wid >> 2;          // 0..1  (m dir, 64 rows each)
    const int wn   = wid & 3;           // 0..3  (n dir, 32 cols each)

    const int m0 = blockIdx.x * 128;
    const int n0 = blockIdx.y * 128;
    const __nv_bfloat16* Abase = A3 + (size_t)m0 * K3;
    const __nv_bfloat16* Bbase = B3 + (size_t)n0 * K3;

    // copy mapping: thread -> (row, two 16B segments)
    const int crow = tid >> 1;
    const int cs0  = (tid & 1) * 2;

    float acc[4][4][4];
#pragma unroll
    for (int i = 0; i < 4; i++)
#pragma unroll
        for (int j = 0; j < 4; j++)
#pragma unroll
            for (int q = 0; q < 4; q++) acc[i][j][q] = 0.0f;

    const int nc = K3 >> 5;

    // ldmatrix per-lane addresses (constant parts)
    const uint32_t a_row = (uint32_t)(wm * 64 + (lane & 15));
    const uint32_t a_k8  = (uint32_t)((lane >> 4) << 3);
    const uint32_t b_row = (uint32_t)(wn * 32 + (lane & 7));
    const uint32_t b_k8  = (uint32_t)(((lane >> 3) & 1) << 3);

    // prologue: chunk 0 -> buffer 0
    {
        const __nv_bfloat16* ga = Abase + (size_t)crow * K3;
        const __nv_bfloat16* gb = Bbase + (size_t)crow * K3;
#pragma unroll
        for (int s = cs0; s < cs0 + 2; s++) {
            cpa16(sb + crow * GM_ROWB + s * 16, ga + s * 8);
            cpa16(sb + GM_MATB + crow * GM_ROWB + s * 16, gb + s * 8);
        }
        cp_commit();
    }

    for (int c = 0; c < nc; c++) {
        const int buf = c & 1;
        if (c + 1 < nc) {
            const int nbuf = (c + 1) & 1;
            const uint32_t abuf = sb + nbuf * GM_BUFB;
            const __nv_bfloat16* ga = Abase + (size_t)crow * K3 + (c + 1) * 32;
            const __nv_bfloat16* gb = Bbase + (size_t)crow * K3 + (c + 1) * 32;
#pragma unroll
            for (int s = cs0; s < cs0 + 2; s++) {
                cpa16(abuf + crow * GM_ROWB + s * 16, ga + s * 8);
                cpa16(abuf + GM_MATB + crow * GM_ROWB + s * 16, gb + s * 8);
            }
            cp_commit();
            cp_wait<1>();
        } else {
            cp_wait<0>();
        }
        __syncthreads();

        const uint32_t sa = sb + buf * GM_BUFB;
        const uint32_t sbm = sa + GM_MATB;
#pragma unroll
        for (int kf = 0; kf < 2; kf++) {
            uint32_t afr[4][4], bfr[4][2];
            const uint32_t ak = (uint32_t)(kf * 16) + a_k8;
            const uint32_t bk = (uint32_t)(kf * 16) + b_k8;
#pragma unroll
            for (int mi = 0; mi < 4; mi++)
                ldsm_x4(afr[mi], sa + (a_row + mi * 16) * GM_ROWB + ak * 2);
#pragma unroll
            for (int ni = 0; ni < 4; ni++)
                ldsm_x2(bfr[ni], sbm + (b_row + ni * 8) * GM_ROWB + bk * 2);
#pragma unroll
            for (int mi = 0; mi < 4; mi++)
#pragma unroll
                for (int ni = 0; ni < 4; ni++)
                    mma16816(acc[mi][ni], afr[mi], bfr[ni]);
        }
        __syncthreads();
    }

    // epilogue: bias + store (optionally row-permuted)
    float* C = buf_ptr<CSEL>(Cext);
#pragma unroll
    for (int mi = 0; mi < 4; mi++) {
        const int r0 = m0 + wm * 64 + mi * 16 + (lane >> 2);
#pragma unroll
        for (int ni = 0; ni < 4; ni++) {
            const int cc = n0 + wn * 32 + ni * 8 + (lane & 3) * 2;
            const float bx = bias[cc], by = bias[cc + 1];
            int orow0 = PERMUTE ? ((r0 & (B_ - 1)) * T_ + (r0 >> 4)) : r0;
            int r1 = r0 + 8;
            int orow1 = PERMUTE ? ((r1 & (B_ - 1)) * T_ + (r1 >> 4)) : r1;
            float2 v0 = make_float2(acc[mi][ni][0] + bx, acc[mi][ni][1] + by);
            float2 v1 = make_float2(acc[mi][ni][2] + bx, acc[mi][ni][3] + by);
            *reinterpret_cast<float2*>(C + (size_t)orow0 * N + cc) = v0;
            *reinterpret_cast<float2*>(C + (size_t)orow1 * N + cc) = v1;
        }
    }
}

// ---------------------------------------------------------------------------
// Persistent layer-0 scan: one kernel, software grid barriers.
// 192 blocks = 24 n-tiles x 8 k-tiles; each caches its Wh0 slice in SMEM.
// ---------------------------------------------------------------------------
__device__ __forceinline__ void grid_sync_(int total)
{
    __syncthreads();
    if (threadIdx.x == 0) {
        __threadfence();
        unsigned gen = *((volatile unsigned*)&g_gen);
        unsigned t = atomicAdd(&g_cnt, 1u);
        if (t == (unsigned)(total - 1)) {
            g_cnt = 0;
            __threadfence();
            *((volatile unsigned*)&g_gen) = gen + 1;
        } else {
            while (*((volatile unsigned*)&g_gen) == gen) __nanosleep(32);
            __threadfence();
        }
    }
    __syncthreads();
}

__device__ __forceinline__ void scan_combine(int t, const float* __restrict__ bh0,
                                             int nb, int tid)
{
    int i = nb * 256 + tid;              // 0..16383
    int b = i >> 10;
    int j = i & (H_ - 1);
    float ghr = bh0[j], ghz = bh0[H_ + j], ghn = bh0[2 * H_ + j];
    if (t > 0) {
#pragma unroll
        for (int ks = 0; ks < KS_; ks++) {
            const float* gp = g_Gpart + (size_t)ks * (16 * H3) + (size_t)b * H3 + j;
            ghr += gp[0];
            ghz += gp[H_];
            ghn += gp[2 * H_];
        }
    }
    const float* gx = g_GX0 + (size_t)(t * B_ + b) * H3 + j;
    float r = sigmoidf_(gx[0]      + ghr);
    float z = sigmoidf_(gx[H_]     + ghz);
    float n = tanhf   (gx[2 * H_] + r * ghn);
    float hp = (t > 0) ? g_H0[(size_t)((t - 1) * B_ + b) * H_ + j] : 0.0f;
    g_H0[(size_t)(t * B_ + b) * H_ + j] = (1.0f - z) * n + z * hp;
}

#define SCAN_SMEM (65536 + 8704)   // W slice 128x128 f32 + H tile 128x17 f32

__global__ __launch_bounds__(256, 2) void scan_kernel(
    const float* __restrict__ Wh, const float* __restrict__ bh0)
{
    extern __shared__ float dsm[];
    float* Wsh = dsm;               // [kk][c] 128x128
    float* Hsh = dsm + 16384;       // [kk][r] 128x17 (padded)

    const int nb  = blockIdx.x;
    const int tid = threadIdx.x;
    const int ntile = nb % 24;
    const int ktile = nb / 24;
    const int n0 = ntile * 128;
    const int k0 = ktile * 128;

    // cache Wh0 slice [k0:k0+128][n0:n0+128] once (float4, coalesced)
#pragma unroll
    for (int i = 0; i < 16; i++) {
        int e4 = i * 256 + tid;              // 0..4095 float4s
        int elem = e4 * 4;
        int kk = elem >> 7;
        int c  = elem & 127;
        *reinterpret_cast<float4*>(&Wsh[elem]) =
            *reinterpret_cast<const float4*>(&Wh[(size_t)(k0 + kk) * H3 + n0 + c]);
    }

    const int r  = tid >> 4;          // 0..15 output row
    const int c0 = (tid & 15) * 8;    // 8 output cols

    // t = 0: no recurrent term
    if (nb < 64) scan_combine(0, bh0, nb, tid);
    grid_sync_(SCAN_BLOCKS);

    for (int t = 1; t < T_; t++) {
        // load h_prev[16][k0:k0+128] transposed into Hsh[kk][r]
        const float* hprev = g_H0 + (size_t)(t - 1) * B_ * H_;
#pragma unroll
        for (int i = 0; i < 8; i++) {
            int e = i * 256 + tid;           // 0..2047
            int rr = e >> 7;
            int kk = e & 127;
            Hsh[kk * 17 + rr] = hprev[(size_t)rr * H_ + k0 + kk];
        }
        __syncthreads();

        float acc[8];
#pragma unroll
        for (int j = 0; j < 8; j++) acc[j] = 0.0f;
#pragma unroll 4
        for (int kk = 0; kk < 128; kk++) {
            float h = Hsh[kk * 17 + r];
            float4 w0 = *reinterpret_cast<const float4*>(&Wsh[kk * 128 + c0]);
            float4 w1 = *reinterpret_cast<const float4*>(&Wsh[kk * 128 + c0 + 4]);
            acc[0] += h * w0.x; acc[1] += h * w0.y;
            acc[2] += h * w0.z; acc[3] += h * w0.w;
            acc[4] += h * w1.x; acc[5] += h * w1.y;
            acc[6] += h * w1.z; acc[7] += h * w1.w;
        }
        float* outp = g_Gpart + (size_t)ktile * (16 * H3) + (size_t)r * H3 + n0 + c0;
        *reinterpret_cast<float4*>(outp)     = make_float4(acc[0], acc[1], acc[2], acc[3]);
        *reinterpret_cast<float4*>(outp + 4) = make_float4(acc[4], acc[5], acc[6], acc[7]);

        grid_sync_(SCAN_BLOCKS);
        if (nb < 64) scan_combine(t, bh0, nb, tid);
        grid_sync_(SCAN_BLOCKS);
    }
}

// ---------------------------------------------------------------------------
// Layer-1 GRU elementwise (input == hidden == h0seq, per reference)
// ---------------------------------------------------------------------------
__global__ void gru1_elem()
{
    size_t i = (size_t)blockIdx.x * blockDim.x + threadIdx.x;
    size_t m = i >> 10;
    int    j = (int)(i & (H_ - 1));
    const float* gx = g_G1x + m * H3 + j;
    const float* gh = g_G1h + m * H3 + j;
    float r = sigmoidf_(gx[0]      + gh[0]);
    float z = sigmoidf_(gx[H_]     + gh[H_]);
    float n = tanhf   (gx[2 * H_] + r * gh[2 * H_]);
    float h = g_H0[i];
    g_H1[i] = (1.0f - z) * n + z * h;
}

__global__ void write_hidden(float* __restrict__ out)
{
    int i = blockIdx.x * blockDim.x + threadIdx.x;
    size_t base = (size_t)(T_ - 1) * B_ * H_;
    float v = (i < B_ * H_) ? g_H0[base + i] : g_H1[base + (i - B_ * H_)];
    out[(size_t)B_ * T_ * V_ + i] = v;
}

// ---------------------------------------------------------------------------
// kernel_launch
// ---------------------------------------------------------------------------
extern "C" void kernel_launch(void* const* d_in, const int* in_sizes, int n_in,
                              void* d_out, int out_size)
{
    const int*   x   = (const int*)  d_in[0];
    const float* emb = (const float*)d_in[1];
    const float* Wx0 = (const float*)d_in[2];
    const float* Wh0 = (const float*)d_in[3];
    const float* bx0 = (const float*)d_in[4];
    const float* bh0 = (const float*)d_in[5];
    const float* Wx1 = (const float*)d_in[6];
    const float* Wh1 = (const float*)d_in[7];
    const float* bx1 = (const float*)d_in[8];
    const float* bh1 = (const float*)d_in[9];
    const float* fcW = (const float*)d_in[10];
    const float* fcb = (const float*)d_in[11];
    float* out = (float*)d_out;

    cudaFuncSetAttribute(scan_kernel, cudaFuncAttributeMaxDynamicSharedMemorySize, SCAN_SMEM);

    __nv_bfloat16 *pWx0t, *pWx1t, *pWh1t, *pFcWt, *pA3;
    cudaGetSymbolAddress((void**)&pWx0t, g_B3_Wx0);
    cudaGetSymbolAddress((void**)&pWx1t, g_B3_Wx1);
    cudaGetSymbolAddress((void**)&pWh1t, g_B3_Wh1);
    cudaGetSymbolAddress((void**)&pFcWt, g_B3_fcW);
    cudaGetSymbolAddress((void**)&pA3,   g_A3);

    dim3 cb(32, 8);
    // 0) weight conversions [K][N] -> [N][3K] bf16 hi/lo
    conv_B3<<<dim3(E_ / 32, H3 / 32), cb>>>(Wx0, pWx0t, E_, H3);
    conv_B3<<<dim3(H_ / 32, H3 / 32), cb>>>(Wx1, pWx1t, H_, H3);
    conv_B3<<<dim3(H_ / 32, H3 / 32), cb>>>(Wh1, pWh1t, H_, H3);
    conv_B3<<<dim3(H_ / 32, V_ / 32), cb>>>(fcW, pFcWt, H_, V_);

    // 1) gx0: gather(emb,x) -> A3 hi/lo, tensor GEMM -> g_GX0 (+bx0)
    conv_A3<BUF_EXT, true, 9><<<(4096 * E_) / 256, 256>>>(emb, x);
    gemm_mma<BUF_GX0, false><<<dim3(32, H3 / 128), 256>>>(
        pA3, pWx0t, bx0, nullptr, H3, 3 * E_);

    // 2) sequential layer-0 scan: ONE persistent kernel (grid barriers inside)
    scan_kernel<<<SCAN_BLOCKS, 256, SCAN_SMEM>>>(Wh0, bh0);

    // 3) layer 1 (time-parallel): H0 -> A3, two tensor GEMMs, elementwise
    conv_A3<BUF_H0, false, 10><<<(4096 * H_) / 256, 256>>>(nullptr, nullptr);
    gemm_mma<BUF_G1X, false><<<dim3(32, H3 / 128), 256>>>(
        pA3, pWx1t, bx1, nullptr, H3, 3 * H_);
    gemm_mma<BUF_G1H, false><<<dim3(32, H3 / 128), 256>>>(
        pA3, pWh1t, bh1, nullptr, H3, 3 * H_);
    gru1_elem<<<(4096 * 1024) / 256, 256>>>();

    // 4) logits: H1 -> A3, tensor GEMM with permuted rows -> out (+fcb)
    conv_A3<BUF_H1, false, 10><<<(4096 * H_) / 256, 256>>>(nullptr, nullptr);
    gemm_mma<BUF_EXT, true><<<dim3(32, V_ / 128), 256>>>(
        pA3, pFcWt, fcb, out, V_, 3 * H_);

    // 5) final hidden states
    write_hidden<<<(2 * B_ * H_) / 256, 256>>>(out);
}